// round 2
// baseline (speedup 1.0000x reference)
#include <cuda_runtime.h>
#include <math.h>

#define POOLK 7
#define HH 50
#define WW 50
#define CC 512
#define NROIS 300
#define NPOS (HH * WW)

// Scratch for channel-max map (device global; no allocation allowed).
__device__ float g_fmax[NPOS];

// Kernel 1: fmax[h][w] = max_c feature_maps[h][w][c]
// One warp per spatial position; 512 contiguous floats -> 4 x float4 per lane.
__global__ void __launch_bounds__(256) fmax_kernel(const float* __restrict__ fm) {
    int gwarp = (blockIdx.x * blockDim.x + threadIdx.x) >> 5;
    int lane = threadIdx.x & 31;
    if (gwarp >= NPOS) return;
    const float4* p = reinterpret_cast<const float4*>(fm + (size_t)gwarp * CC);
    float m = -INFINITY;
#pragma unroll
    for (int i = 0; i < 4; ++i) {
        float4 v = p[lane + 32 * i];
        m = fmaxf(m, fmaxf(fmaxf(v.x, v.y), fmaxf(v.z, v.w)));
    }
#pragma unroll
    for (int o = 16; o; o >>= 1)
        m = fmaxf(m, __shfl_xor_sync(0xffffffffu, m, o));
    if (lane == 0) g_fmax[gwarp] = m;
}

// Kernel 2: one block per ROI. Stage fmax in shared, compute 49 bin maxima,
// broadcast each over 512 channels into the output (coalesced float4 stores).
__global__ void __launch_bounds__(256) roi_kernel(const float* __restrict__ rois,
                                                  float* __restrict__ out) {
    __shared__ float sfm[NPOS];
    __shared__ float spool[POOLK * POOLK];

    const int roi = blockIdx.x;
    const int tid = threadIdx.x;

    for (int i = tid; i < NPOS; i += blockDim.x) sfm[i] = g_fmax[i];

    // ROI integer bounds (truncation matches astype(int32) for nonneg values;
    // *0.0625f is exact, identical to /16).
    const float* r = rois + roi * 5;
    const int x1 = (int)(r[1] * 0.0625f);
    const int y1 = (int)(r[2] * 0.0625f);
    const int x2 = (int)(r[3] * 0.0625f);
    const int y2 = (int)(r[4] * 0.0625f);
    const int rh = y2 - y1 + 1;
    const int rw = x2 - x1 + 1;

    __syncthreads();

    if (tid < POOLK * POOLK) {
        const int ph = tid / POOLK;
        const int pw = tid % POOLK;
        int hs = min(max(y1 + (ph * rh) / POOLK, 0), HH);
        int he = min(max(y1 + ((ph + 1) * rh + POOLK - 1) / POOLK, 0), HH);
        int ws = min(max(x1 + (pw * rw) / POOLK, 0), WW);
        int we = min(max(x1 + ((pw + 1) * rw + POOLK - 1) / POOLK, 0), WW);
        float m = -INFINITY;
        for (int h = hs; h < he; ++h) {
            const float* row = sfm + h * WW;
            for (int w = ws; w < we; ++w) m = fmaxf(m, row[w]);
        }
        spool[tid] = m;
    }
    __syncthreads();

    // Broadcast-write: 49 bins * 512 ch = 49*128 float4 per ROI, coalesced.
    float4* o = reinterpret_cast<float4*>(out + (size_t)roi * POOLK * POOLK * CC);
    const int n4 = POOLK * POOLK * (CC / 4);  // 6272
    for (int idx = tid; idx < n4; idx += blockDim.x) {
        float v = spool[idx >> 7];  // idx / 128 -> bin
        o[idx] = make_float4(v, v, v, v);
    }
}

extern "C" void kernel_launch(void* const* d_in, const int* in_sizes, int n_in,
                              void* d_out, int out_size) {
    // Identify inputs by size: rois = 300*5 = 1500, feature_maps = 50*50*512.
    const float* rois = (const float*)d_in[0];
    const float* fm = (const float*)d_in[1];
    if (n_in >= 2 && in_sizes[0] > in_sizes[1]) {
        rois = (const float*)d_in[1];
        fm = (const float*)d_in[0];
    }
    float* out = (float*)d_out;

    const int warps = NPOS;  // one warp per position
    const int threads = 256;
    const int blocks1 = (warps * 32 + threads - 1) / threads;  // 313
    fmax_kernel<<<blocks1, threads>>>(fm);
    roi_kernel<<<NROIS, threads>>>(rois, out);
}